// round 13
// baseline (speedup 1.0000x reference)
#include <cuda_runtime.h>
#include <cstdint>

// Qwen3MoeMLP: out = down( silu(x @ gate^T) * (x @ up^T) )
// T=8192, H=2048, I=768, fp32. TF32 mma.sync (tcgen05 unavailable: PTX target
// is sm_103 non-'a').
// R13: R12 + B repacked in k8-PAIRS -> one LDS.128 feeds 4 MMAs (B LDS count
//      halved). A register pipeline holds even/odd k8 fragment pairs.

#define T_DIM 8192
#define H_DIM 2048
#define I_DIM 768
#define KH8   (H_DIM / 8)     // 256 k8-tiles over H
#define KI8   (I_DIM / 8)     // 96  k8-tiles over I
#define KT1   (H_DIM / 64)    // 32 kt-iterations (gateup)
#define KT2   (I_DIM / 64)    // 12 kt-iterations (down)
#define BSTAGE 32768          // B bytes per stage: 16 nt x 4 kp x 32 lanes x 16B
#define NSTG   3
#define GU_BLOCKS 768         // 64 bm x 12 bn (N = 2*I interleaved / 128)
#define DN_BLOCKS 1024        // 64 bm x 16 bn (N = H / 128)

// Static device scratch (no allocations allowed).
// A-pack: [mt][k8][lane][4 floats]            (m16k8 fragments)
// B-pack: [nt][k8pair][lane][4 floats]        (two n8k8 fragments interleaved:
//          .xy = b of even k8, .zw = b of odd k8)
// g_wgu interleaves gate/up: out_nt = 2q -> gate tile q, 2q+1 -> up tile q.
__device__ __align__(256) float g_xa [(size_t)T_DIM * H_DIM];
__device__ __align__(256) float g_wgu[(size_t)2 * I_DIM * H_DIM];
__device__ __align__(256) float g_wdb[(size_t)H_DIM * I_DIM];
__device__ __align__(256) float g_ha [(size_t)T_DIM * I_DIM];
__device__ unsigned g_cnt[64];          // rowblock completion counters

__device__ __forceinline__ float f2tf(float f) {
    unsigned u;
    asm("cvt.rna.tf32.f32 %0, %1;" : "=r"(u) : "f"(f));
    return __uint_as_float(u);
}
__device__ __forceinline__ float4 round4(float4 v) {
    return make_float4(f2tf(v.x), f2tf(v.y), f2tf(v.z), f2tf(v.w));
}
__device__ __forceinline__ void cp16(uint32_t s, const void* g) {
    asm volatile("cp.async.cg.shared.global [%0], [%1], 16;\n" :: "r"(s), "l"(g));
}
__device__ __forceinline__ void cp_commit() {
    asm volatile("cp.async.commit_group;\n" ::);
}
template <int N>
__device__ __forceinline__ void cp_wait() {
    asm volatile("cp.async.wait_group %0;\n" :: "n"(N));
}
__device__ __forceinline__ uint4 lds128(uint32_t a) {
    uint4 v;
    asm volatile("ld.shared.v4.b32 {%0,%1,%2,%3}, [%4];"
                 : "=r"(v.x), "=r"(v.y), "=r"(v.z), "=r"(v.w) : "r"(a));
    return v;
}
__device__ __forceinline__ void mma8(float* c, const uint4 a, const uint32_t b0,
                                     const uint32_t b1) {
    asm volatile(
        "mma.sync.aligned.m16n8k8.row.col.f32.tf32.tf32.f32 "
        "{%0,%1,%2,%3}, {%4,%5,%6,%7}, {%8,%9}, {%0,%1,%2,%3};\n"
        : "+f"(c[0]), "+f"(c[1]), "+f"(c[2]), "+f"(c[3])
        : "r"(a.x), "r"(a.y), "r"(a.z), "r"(a.w), "r"(b0), "r"(b1));
}

// ============================================================================
// Prep: round to tf32 grid, pack to fragment order (coalesced smem staging).
// Blocks [0,2048): X -> A-pack. [2048,3584): Wg/Wu -> paired B-pack interleaved.
// [3584,4352): Wd -> paired B-pack. Also resets rowblock counters.
// ============================================================================
__global__ void __launch_bounds__(256)
prep_kernel(const float* __restrict__ X,  const float* __restrict__ Wg,
            const float* __restrict__ Wu, const float* __restrict__ Wd)
{
    extern __shared__ float sm[];
    const int tid = threadIdx.x;
    const int bid = blockIdx.x;

    if (bid == 0 && tid < 64) g_cnt[tid] = 0;

    if (bid < 2048) {
        // ---- X -> A-pack ----
        const int mt = bid >> 2;        // 0..511 (m16 tiles)
        const int kc = bid & 3;         // 512-col chunk
        const float* src = X + (size_t)mt * 16 * H_DIM + kc * 512;
#pragma unroll
        for (int i = 0; i < 8; i++) {
            const int q = tid + 256 * i;
            const int r = q >> 7, c4 = q & 127;
            float4 v = round4(__ldg((const float4*)(src + (size_t)r * H_DIM) + c4));
            *(float4*)(sm + r * 516 + c4 * 4) = v;
        }
        __syncthreads();
#pragma unroll
        for (int i = 0; i < 8; i++) {
            const int f = tid + 256 * i;
            const int ktl = f >> 5, lane = f & 31;
            const int g = lane >> 2, tg = lane & 3;
            const int c = ktl * 8 + tg;
            float4 v = make_float4(sm[g * 516 + c],     sm[(g + 8) * 516 + c],
                                   sm[g * 516 + c + 4], sm[(g + 8) * 516 + c + 4]);
            ((float4*)g_xa)[((size_t)mt * KH8 + kc * 64 + ktl) * 32 + lane] = v;
        }
    } else {
        // ---- W -> paired B-pack ----
        const int b2 = bid - 2048;
        const float* W;
        float* dst;
        int LD, KPLD;          // KPLD = number of k8-pairs in K
        size_t out_nt;
        int kc;
        if (b2 < 1536) {
            const int sel = (b2 < 768) ? 0 : 1;     // 0=gate, 1=up
            W = sel ? Wu : Wg;
            dst = g_wgu;
            LD = H_DIM; KPLD = KH8 / 2;             // 128 pairs
            const int r = (b2 < 768) ? b2 : b2 - 768;   // NOT & 767 (768 != 2^n)
            const int nt = r >> 3;                  // 0..95
            kc = r & 7;                             // 8 chunks x 256 cols (16 pairs)
            out_nt = 2 * (size_t)nt + sel;          // interleave
            W += (size_t)nt * 8 * LD;
        } else {
            W = Wd; dst = g_wdb;
            LD = I_DIM; KPLD = KI8 / 2;             // 48 pairs
            const int r = b2 - 1536;
            const int nt = r / 3;                   // 0..255
            kc = r % 3;                             // 3 chunks x 256 cols
            out_nt = (size_t)nt;
            W += (size_t)nt * 8 * LD;
        }
        const float* src = W + kc * 256;
#pragma unroll
        for (int i = 0; i < 2; i++) {
            const int q = tid + 256 * i;
            const int r = q >> 6, c4 = q & 63;
            float4 v = round4(__ldg((const float4*)(src + (size_t)r * LD) + c4));
            *(float4*)(sm + r * 260 + c4 * 4) = v;
        }
        __syncthreads();
        // 16 k8-pairs x 32 lanes = 512 float4 writes (2 iterations).
#pragma unroll
        for (int i = 0; i < 2; i++) {
            const int f = tid + 256 * i;
            const int kpl = f >> 5, lane = f & 31;
            const int g = lane >> 2, tg = lane & 3;
            const int c = kpl * 16 + tg;            // even k8 base col
            float4 v = make_float4(sm[g * 260 + c],     sm[g * 260 + c + 4],
                                   sm[g * 260 + c + 8], sm[g * 260 + c + 12]);
            ((float4*)dst)[(out_nt * KPLD + kc * 16 + kpl) * 32 + lane] = v;
        }
    }
}

// ============================================================================
// GEMM body: C tile 128 x 128, mt=2 x nt=8 per warp. BK=64 (4 k8-pairs)/stage.
// A via LDG.128 register pipeline (one k8-pair deep);
// B via 3-stage cp.async ring, one LDS.128 -> 4 MMAs.
// GU: A=g_xa, B=g_wgu (interleaved), SiLU-pair epilogue -> g_ha; release cnt.
// DN: B prefetch first, acquire-spin on cnt, A=g_ha, B=g_wdb -> Out.
// ============================================================================
template <int K8S, int KT, bool GU>
__device__ __forceinline__ void gemm_body(int bid, uint32_t sb, float* __restrict__ Out)
{
    const int tid  = threadIdx.x;
    const int lane = tid & 31;
    const int warp = tid >> 5;
    const int wm = warp & 3;
    const int wn = warp >> 2;
    const int g  = lane >> 2;
    const int tg = lane & 3;

    const int NBN = GU ? 12 : 16;
    const int bmblk = bid / NBN;
    const int bnblk = bid % NBN;
    const size_t mt0 = (size_t)bmblk * 8;
    const size_t nt0 = (size_t)bnblk * 16;

    const float* Apack = GU ? g_xa : g_ha;
    const float* Bpack = GU ? g_wgu : g_wdb;
    const int KP = K8S / 2;                 // k8-pairs in K

    // Stage layout: [ntl(16)][kp(4)][lane(32)] x 16B = 32KB.
    auto load_B = [&](int s, int kt) {
        const uint32_t st = sb + s * BSTAGE;
#pragma unroll
        for (int i = 0; i < 8; i++) {
            const int q = tid + 256 * i;                 // 0..2047 granules of 16B
            const int lq = q & 31, kp = (q >> 5) & 3, ntl = q >> 7;
            const float* src = Bpack +
                (((nt0 + ntl) * KP + (size_t)kt * 4 + kp) * 32 + lq) * 4;
            cp16(st + q * 16, src);
        }
    };

    // Weight/B prefetch does not depend on gateup output -> issue before acquire.
    load_B(0, 0); cp_commit();
    load_B(1, 1); cp_commit();

    if (!GU) {
        // Acquire: wait until all 12 gateup tiles of this rowblock released.
        if (tid == 0) {
            unsigned v;
            const unsigned* p = &g_cnt[bmblk];
            do {
                asm volatile("ld.acquire.gpu.global.u32 %0, [%1];"
                             : "=r"(v) : "l"(p) : "memory");
                if (v < 12u) __nanosleep(128);
            } while (v < 12u);
        }
        __syncthreads();
    }

    const uint4* ap0 = (const uint4*)Apack + ((mt0 + wm * 2 + 0) * K8S) * 32 + lane;
    const uint4* ap1 = (const uint4*)Apack + ((mt0 + wm * 2 + 1) * K8S) * 32 + lane;

    float acc[2][8][4];
#pragma unroll
    for (int i = 0; i < 2; i++)
#pragma unroll
        for (int j = 0; j < 8; j++)
#pragma unroll
            for (int k = 0; k < 4; k++) acc[i][j][k] = 0.f;

    // A register pipeline: current even/odd k8 fragments + next-pair prefetch.
    const int LASTF = KT * 8 - 1;
    uint4 aE0 = __ldg(ap0);        // even k8, mt 0
    uint4 aE1 = __ldg(ap1);        // even k8, mt 1
    uint4 aO0 = __ldg(ap0 + 32);   // odd  k8, mt 0
    uint4 aO1 = __ldg(ap1 + 32);   // odd  k8, mt 1

    int sc = 0, sl = 2;
    for (int kt = 0; kt < KT; ++kt) {
        cp_wait<1>();
        __syncthreads();
        if (kt + 2 < KT) load_B(sl, kt + 2);
        cp_commit();
        const uint32_t sB = sb + sc * BSTAGE;
#pragma unroll
        for (int kp = 0; kp < 4; kp++) {
            int nf = kt * 8 + kp * 2 + 2;            // next even k8 fragment
            int f0 = nf     > LASTF ? LASTF : nf;
            int f1 = nf + 1 > LASTF ? LASTF : nf + 1;
            uint4 nE0 = __ldg(ap0 + (size_t)f0 * 32);
            uint4 nE1 = __ldg(ap1 + (size_t)f0 * 32);
            uint4 nO0 = __ldg(ap0 + (size_t)f1 * 32);
            uint4 nO1 = __ldg(ap1 + (size_t)f1 * 32);
#pragma unroll
            for (int t = 0; t < 8; t++) {
                const int ntl = wn * 8 + t;
                uint4 bb = lds128(sB + ((ntl * 4 + kp) * 32 + lane) * 16);
                mma8(acc[0][t], aE0, bb.x, bb.y);
                mma8(acc[1][t], aE1, bb.x, bb.y);
                mma8(acc[0][t], aO0, bb.z, bb.w);
                mma8(acc[1][t], aO1, bb.z, bb.w);
            }
            aE0 = nE0; aE1 = nE1; aO0 = nO0; aO1 = nO1;
        }
        if (++sc == NSTG) sc = 0;
        if (++sl == NSTG) sl = 0;
    }

    if (GU) {
        // h = silu(gate)*up (tf32-rounded), A-pack order.
        // acc[tm][2j]=gate tile q, acc[tm][2j+1]=up tile q, q=bnblk*8+wn*4+j.
#pragma unroll
        for (int tm = 0; tm < 2; tm++) {
#pragma unroll
            for (int j = 0; j < 4; j++) {
                const size_t mt_h = mt0 + wm * 2 + tm;
                const size_t kt_h = (size_t)bnblk * 8 + wn * 4 + j;
                float h[4];
#pragma unroll
                for (int i = 0; i < 4; i++) {
                    const float gv = acc[tm][2 * j][i];
                    const float uv = acc[tm][2 * j + 1][i];
                    h[i] = f2tf(gv * uv / (1.0f + __expf(-gv)));
                }
                const int L  = g * 4 + ((2 * tg) & 3);
                const int j0 = (tg >= 2) ? 2 : 0;
                float* base = g_ha + (mt_h * KI8 + kt_h) * 128;
                *(float2*)(base + L * 4 + j0)       = make_float2(h[0], h[2]);
                *(float2*)(base + (L + 1) * 4 + j0) = make_float2(h[1], h[3]);
            }
        }
        // Release: all stores visible, then bump rowblock counter.
        __threadfence();
        __syncthreads();
        if (tid == 0)
            asm volatile("red.release.gpu.global.add.u32 [%0], %1;"
                         :: "l"(&g_cnt[bmblk]), "r"(1u) : "memory");
    } else {
        const int bm = bmblk * 128;
        const int bn = bnblk * 128;
#pragma unroll
        for (int tm = 0; tm < 2; tm++) {
#pragma unroll
            for (int tn = 0; tn < 8; tn++) {
                const int r0 = bm + wm * 32 + tm * 16 + g;
                const int c0 = bn + wn * 64 + tn * 8 + 2 * tg;
                *(float2*)(Out + (size_t)r0 * H_DIM + c0) =
                    make_float2(acc[tm][tn][0], acc[tm][tn][1]);
                *(float2*)(Out + (size_t)(r0 + 8) * H_DIM + c0) =
                    make_float2(acc[tm][tn][2], acc[tm][tn][3]);
            }
        }
    }
}

__global__ void __launch_bounds__(256, 2)
mlp_kernel(float* __restrict__ Out)
{
    extern __shared__ __align__(16) char smem[];
    const uint32_t sb = (uint32_t)__cvta_generic_to_shared(smem);
    const int bid = blockIdx.x;
    if (bid < GU_BLOCKS) gemm_body<KH8, KT1, true >(bid, sb, Out);
    else                 gemm_body<KI8, KT2, false>(bid - GU_BLOCKS, sb, Out);
}

// ============================================================================
// Launch
// ============================================================================
extern "C" void kernel_launch(void* const* d_in, const int* in_sizes, int n_in,
                              void* d_out, int out_size)
{
    const float* x  = (const float*)d_in[0];
    const float* wg = (const float*)d_in[1];
    const float* wu = (const float*)d_in[2];
    const float* wd = (const float*)d_in[3];
    float* out = (float*)d_out;

    const int prep_smem = 16 * 516 * 4;       // 33024
    const int gemm_smem = NSTG * BSTAGE;      // 98304
    cudaFuncSetAttribute(prep_kernel, cudaFuncAttributeMaxDynamicSharedMemorySize, prep_smem);
    cudaFuncSetAttribute(mlp_kernel,  cudaFuncAttributeMaxDynamicSharedMemorySize, gemm_smem);

    prep_kernel<<<4352, 256, prep_smem>>>(x, wg, wu, wd);
    mlp_kernel<<<GU_BLOCKS + DN_BLOCKS, 256, gemm_smem>>>(out);
}

// round 14
// speedup vs baseline: 1.1010x; 1.1010x over previous
#include <cuda_runtime.h>
#include <cstdint>

// Qwen3MoeMLP: out = down( silu(x @ gate^T) * (x @ up^T) )
// T=8192, H=2048, I=768, fp32. TF32 mma.sync (tcgen05 unavailable: PTX target
// is sm_103 non-'a').
// R14: R12 compute core (374us known-good) + mbarrier producer/consumer
//      pipeline replacing per-kt cp_wait+__syncthreads lockstep:
//      full[s]: cp.async.mbarrier.arrive.noinc (data-arrival wait)
//      empty[s]: per-thread arrive after consuming stage (overwrite guard)

#define T_DIM 8192
#define H_DIM 2048
#define I_DIM 768
#define KH8   (H_DIM / 8)     // 256 k8-tiles over H
#define KI8   (I_DIM / 8)     // 96  k8-tiles over I
#define KT1   (H_DIM / 64)    // 32 kt-iterations (gateup)
#define KT2   (I_DIM / 64)    // 12 kt-iterations (down)
#define BSTAGE 32768          // B bytes per pipeline stage (16 nt x 8 k8 x 256B)
#define NSTG   3
#define GU_BLOCKS 768         // 64 bm x 12 bn (N = 2*I interleaved / 128)
#define DN_BLOCKS 1024        // 64 bm x 16 bn (N = H / 128)

// Static device scratch (no allocations allowed).
// A-pack: [mt][k8][lane][4 floats] (m16k8 frags). B-pack: [nt][k8][lane][2 floats].
// g_wgu interleaves gate/up: out_nt = 2q -> gate tile q, 2q+1 -> up tile q.
__device__ __align__(256) float g_xa [(size_t)T_DIM * H_DIM];
__device__ __align__(256) float g_wgu[(size_t)2 * I_DIM * H_DIM];
__device__ __align__(256) float g_wdb[(size_t)H_DIM * I_DIM];
__device__ __align__(256) float g_ha [(size_t)T_DIM * I_DIM];
__device__ unsigned g_cnt[64];          // rowblock completion counters

__device__ __forceinline__ float f2tf(float f) {
    unsigned u;
    asm("cvt.rna.tf32.f32 %0, %1;" : "=r"(u) : "f"(f));
    return __uint_as_float(u);
}
__device__ __forceinline__ float4 round4(float4 v) {
    return make_float4(f2tf(v.x), f2tf(v.y), f2tf(v.z), f2tf(v.w));
}
__device__ __forceinline__ void cp16(uint32_t s, const void* g) {
    asm volatile("cp.async.cg.shared.global [%0], [%1], 16;\n" :: "r"(s), "l"(g));
}
__device__ __forceinline__ uint2 lds64(uint32_t a) {
    uint2 v;
    asm volatile("ld.shared.v2.b32 {%0,%1}, [%2];" : "=r"(v.x), "=r"(v.y) : "r"(a));
    return v;
}
__device__ __forceinline__ void mma8(float* c, const uint4 a, const uint2 b) {
    asm volatile(
        "mma.sync.aligned.m16n8k8.row.col.f32.tf32.tf32.f32 "
        "{%0,%1,%2,%3}, {%4,%5,%6,%7}, {%8,%9}, {%0,%1,%2,%3};\n"
        : "+f"(c[0]), "+f"(c[1]), "+f"(c[2]), "+f"(c[3])
        : "r"(a.x), "r"(a.y), "r"(a.z), "r"(a.w), "r"(b.x), "r"(b.y));
}

// ---- mbarrier helpers (sm_80/sm_90 era PTX; no tcgen05) ----
__device__ __forceinline__ void mbar_init(uint32_t a, uint32_t cnt) {
    asm volatile("mbarrier.init.shared.b64 [%0], %1;" :: "r"(a), "r"(cnt) : "memory");
}
__device__ __forceinline__ void mbar_arrive(uint32_t a) {
    asm volatile("mbarrier.arrive.shared.b64 _, [%0];" :: "r"(a) : "memory");
}
__device__ __forceinline__ void cpasync_mbar_arrive(uint32_t a) {
    asm volatile("cp.async.mbarrier.arrive.noinc.shared.b64 [%0];" :: "r"(a) : "memory");
}
__device__ __forceinline__ void mbar_wait(uint32_t a, uint32_t parity) {
    asm volatile(
        "{\n .reg .pred P;\n"
        "W%=:\n"
        " mbarrier.try_wait.parity.shared.b64 P, [%0], %1;\n"
        " @P bra D%=;\n"
        " bra W%=;\n"
        "D%=:\n}"
        :: "r"(a), "r"(parity) : "memory");
}

// ============================================================================
// Prep: round to tf32 grid, pack to fragment order (coalesced smem staging).
// Blocks [0,2048): X. [2048,3584): Wg/Wu interleaved. [3584,4352): Wd.
// Also resets rowblock counters (graph replays reuse them).
// ============================================================================
__global__ void __launch_bounds__(256)
prep_kernel(const float* __restrict__ X,  const float* __restrict__ Wg,
            const float* __restrict__ Wu, const float* __restrict__ Wd)
{
    extern __shared__ float sm[];
    const int tid = threadIdx.x;
    const int bid = blockIdx.x;

    if (bid == 0 && tid < 64) g_cnt[tid] = 0;

    if (bid < 2048) {
        // ---- X -> A-pack ----
        const int mt = bid >> 2;        // 0..511 (m16 tiles)
        const int kc = bid & 3;         // 512-col chunk
        const float* src = X + (size_t)mt * 16 * H_DIM + kc * 512;
#pragma unroll
        for (int i = 0; i < 8; i++) {
            const int q = tid + 256 * i;
            const int r = q >> 7, c4 = q & 127;
            float4 v = round4(__ldg((const float4*)(src + (size_t)r * H_DIM) + c4));
            *(float4*)(sm + r * 516 + c4 * 4) = v;
        }
        __syncthreads();
#pragma unroll
        for (int i = 0; i < 8; i++) {
            const int f = tid + 256 * i;
            const int ktl = f >> 5, lane = f & 31;
            const int g = lane >> 2, tg = lane & 3;
            const int c = ktl * 8 + tg;
            float4 v = make_float4(sm[g * 516 + c],     sm[(g + 8) * 516 + c],
                                   sm[g * 516 + c + 4], sm[(g + 8) * 516 + c + 4]);
            ((float4*)g_xa)[((size_t)mt * KH8 + kc * 64 + ktl) * 32 + lane] = v;
        }
    } else {
        // ---- W -> B-pack ----
        const int b2 = bid - 2048;
        const float* W;
        float* dst;
        int LD, KLD;
        size_t out_nt;
        int kc;
        if (b2 < 1536) {
            const int sel = (b2 < 768) ? 0 : 1;     // 0=gate, 1=up
            W = sel ? Wu : Wg;
            dst = g_wgu;
            LD = H_DIM; KLD = KH8;
            const int r = (b2 < 768) ? b2 : b2 - 768;   // NOT & 767 (768 != 2^n)
            const int nt = r >> 3;                  // 0..95
            kc = r & 7;                             // 8 chunks x 256 cols
            out_nt = 2 * (size_t)nt + sel;          // interleave
            W += (size_t)nt * 8 * LD;
        } else {
            W = Wd; dst = g_wdb;
            LD = I_DIM; KLD = KI8;
            const int r = b2 - 1536;
            const int nt = r / 3;                   // 0..255
            kc = r % 3;                             // 3 chunks x 256 cols
            out_nt = (size_t)nt;
            W += (size_t)nt * 8 * LD;
        }
        const float* src = W + kc * 256;
#pragma unroll
        for (int i = 0; i < 2; i++) {
            const int q = tid + 256 * i;
            const int r = q >> 6, c4 = q & 63;
            float4 v = round4(__ldg((const float4*)(src + (size_t)r * LD) + c4));
            *(float4*)(sm + r * 260 + c4 * 4) = v;
        }
        __syncthreads();
#pragma unroll
        for (int i = 0; i < 4; i++) {
            const int f = tid + 256 * i;
            const int ktl = f >> 5, lane = f & 31;
            const int g = lane >> 2, tg = lane & 3;
            const int c = ktl * 8 + tg;
            float2 v = make_float2(sm[g * 260 + c], sm[g * 260 + c + 4]);
            ((float2*)dst)[(out_nt * KLD + kc * 32 + ktl) * 32 + lane] = v;
        }
    }
}

// ============================================================================
// GEMM body: C tile 128 x 128, mt=2 x nt=8 per warp. BK=64 (8 k8) per stage.
// A via LDG.128 register pipeline (2 k8 deep); B via 3-stage cp.async ring
// gated by mbarriers (full = data-arrival, empty = consumers-done).
// GU: A=g_xa, B=g_wgu (interleaved), SiLU-pair epilogue -> g_ha; release cnt.
// DN: B prefetch first, acquire-spin on cnt, A=g_ha, B=g_wdb -> Out.
// ============================================================================
template <int K8S, int KT, bool GU>
__device__ __forceinline__ void gemm_body(int bid, uint32_t sb, float* __restrict__ Out)
{
    const int tid  = threadIdx.x;
    const int lane = tid & 31;
    const int warp = tid >> 5;
    const int wm = warp & 3;
    const int wn = warp >> 2;
    const int g  = lane >> 2;
    const int tg = lane & 3;

    const int NBN = GU ? 12 : 16;
    const int bmblk = bid / NBN;
    const int bnblk = bid % NBN;
    const size_t mt0 = (size_t)bmblk * 8;
    const size_t nt0 = (size_t)bnblk * 16;

    const float* Apack = GU ? g_xa : g_ha;
    const float* Bpack = GU ? g_wgu : g_wdb;

    // mbarriers after the 3 stages: full[s] at mbF+8s, empty[s] at mbE+8s.
    const uint32_t mbF = sb + NSTG * BSTAGE;
    const uint32_t mbE = mbF + 8 * NSTG;
    if (tid == 0) {
#pragma unroll
        for (int s = 0; s < NSTG; s++) {
            mbar_init(mbF + 8 * s, 256);   // 256 async arrives (noinc)
            mbar_init(mbE + 8 * s, 256);   // 256 thread arrives
        }
    }
    __syncthreads();

    // Stage layout: [ntl(16)][k8(8)][lane(32)] x 8B = 32KB.
    auto load_stage = [&](int ktL) {
        const int s = ktL % NSTG;
        if (ktL >= NSTG)                    // stage last consumed at ktL-NSTG
            mbar_wait(mbE + 8 * s, ((ktL / NSTG) & 1) ^ 1);
        const uint32_t st = sb + s * BSTAGE;
#pragma unroll
        for (int i = 0; i < 8; i++) {
            const int q = tid + 256 * i;                 // 0..2047 granules of 16B
            const int pr = q & 15, k8 = (q >> 4) & 7, ntl = q >> 7;
            const float* src = Bpack +
                (((nt0 + ntl) * K8S + (size_t)ktL * 8 + k8) * 32) * 2 + pr * 4;
            cp16(st + q * 16, src);
        }
        cpasync_mbar_arrive(mbF + 8 * s);   // arrive when this thread's cps land
    };

    // Weight/B prefetch does not depend on gateup output -> issue before acquire.
    load_stage(0);
    load_stage(1);

    if (!GU) {
        // Acquire: wait until all 12 gateup tiles of this rowblock released.
        if (tid == 0) {
            unsigned v;
            const unsigned* p = &g_cnt[bmblk];
            do {
                asm volatile("ld.acquire.gpu.global.u32 %0, [%1];"
                             : "=r"(v) : "l"(p) : "memory");
                if (v < 12u) __nanosleep(128);
            } while (v < 12u);
        }
        __syncthreads();
    }

    const uint4* ap0 = (const uint4*)Apack + ((mt0 + wm * 2 + 0) * K8S) * 32 + lane;
    const uint4* ap1 = (const uint4*)Apack + ((mt0 + wm * 2 + 1) * K8S) * 32 + lane;

    float acc[2][8][4];
#pragma unroll
    for (int i = 0; i < 2; i++)
#pragma unroll
        for (int j = 0; j < 8; j++)
#pragma unroll
            for (int k = 0; k < 4; k++) acc[i][j][k] = 0.f;

    // A register pipeline, 2 k8 deep.
    const int LASTF = KT * 8 - 1;
    uint4 a0 = __ldg(ap0);
    uint4 a1 = __ldg(ap1);
    uint4 b0 = __ldg(ap0 + 32);
    uint4 b1 = __ldg(ap1 + 32);

    for (int kt = 0; kt < KT; ++kt) {
        if (kt + 2 < KT) load_stage(kt + 2);
        const int s = kt % NSTG;
        mbar_wait(mbF + 8 * s, (kt / NSTG) & 1);    // data arrived (all threads)
        const uint32_t sB = sb + s * BSTAGE;
#pragma unroll
        for (int k8 = 0; k8 < 8; k8++) {
            int nf = kt * 8 + k8 + 2;
            if (nf > LASTF) nf = LASTF;
            uint4 c0 = __ldg(ap0 + (size_t)nf * 32);
            uint4 c1 = __ldg(ap1 + (size_t)nf * 32);
#pragma unroll
            for (int t = 0; t < 8; t++) {
                const int ntl = wn * 8 + t;
                uint2 b = lds64(sB + ((ntl * 8 + k8) * 32 + lane) * 8);
                mma8(acc[0][t], a0, b);
                mma8(acc[1][t], a1, b);
            }
            a0 = b0; a1 = b1; b0 = c0; b1 = c1;
        }
        mbar_arrive(mbE + 8 * s);                   // done reading stage s
    }

    if (GU) {
        // h = silu(gate)*up (tf32-rounded), A-pack order.
        // acc[tm][2j]=gate tile q, acc[tm][2j+1]=up tile q, q=bnblk*8+wn*4+j.
#pragma unroll
        for (int tm = 0; tm < 2; tm++) {
#pragma unroll
            for (int j = 0; j < 4; j++) {
                const size_t mt_h = mt0 + wm * 2 + tm;
                const size_t kt_h = (size_t)bnblk * 8 + wn * 4 + j;
                float h[4];
#pragma unroll
                for (int i = 0; i < 4; i++) {
                    const float gv = acc[tm][2 * j][i];
                    const float uv = acc[tm][2 * j + 1][i];
                    h[i] = f2tf(gv * uv / (1.0f + __expf(-gv)));
                }
                const int L  = g * 4 + ((2 * tg) & 3);
                const int j0 = (tg >= 2) ? 2 : 0;
                float* base = g_ha + (mt_h * KI8 + kt_h) * 128;
                *(float2*)(base + L * 4 + j0)       = make_float2(h[0], h[2]);
                *(float2*)(base + (L + 1) * 4 + j0) = make_float2(h[1], h[3]);
            }
        }
        // Release: all stores visible, then bump rowblock counter.
        __threadfence();
        __syncthreads();
        if (tid == 0)
            asm volatile("red.release.gpu.global.add.u32 [%0], %1;"
                         :: "l"(&g_cnt[bmblk]), "r"(1u) : "memory");
    } else {
        const int bm = bmblk * 128;
        const int bn = bnblk * 128;
#pragma unroll
        for (int tm = 0; tm < 2; tm++) {
#pragma unroll
            for (int tn = 0; tn < 8; tn++) {
                const int r0 = bm + wm * 32 + tm * 16 + g;
                const int c0 = bn + wn * 64 + tn * 8 + 2 * tg;
                *(float2*)(Out + (size_t)r0 * H_DIM + c0) =
                    make_float2(acc[tm][tn][0], acc[tm][tn][1]);
                *(float2*)(Out + (size_t)(r0 + 8) * H_DIM + c0) =
                    make_float2(acc[tm][tn][2], acc[tm][tn][3]);
            }
        }
    }
}

__global__ void __launch_bounds__(256, 2)
mlp_kernel(float* __restrict__ Out)
{
    extern __shared__ __align__(16) char smem[];
    const uint32_t sb = (uint32_t)__cvta_generic_to_shared(smem);
    const int bid = blockIdx.x;
    if (bid < GU_BLOCKS) gemm_body<KH8, KT1, true >(bid, sb, Out);
    else                 gemm_body<KI8, KT2, false>(bid - GU_BLOCKS, sb, Out);
}

// ============================================================================
// Launch
// ============================================================================
extern "C" void kernel_launch(void* const* d_in, const int* in_sizes, int n_in,
                              void* d_out, int out_size)
{
    const float* x  = (const float*)d_in[0];
    const float* wg = (const float*)d_in[1];
    const float* wu = (const float*)d_in[2];
    const float* wd = (const float*)d_in[3];
    float* out = (float*)d_out;

    const int prep_smem = 16 * 516 * 4;             // 33024
    const int gemm_smem = NSTG * BSTAGE + 64;       // 98368 (stages + mbarriers)
    cudaFuncSetAttribute(prep_kernel, cudaFuncAttributeMaxDynamicSharedMemorySize, prep_smem);
    cudaFuncSetAttribute(mlp_kernel,  cudaFuncAttributeMaxDynamicSharedMemorySize, gemm_smem);

    prep_kernel<<<4352, 256, prep_smem>>>(x, wg, wu, wd);
    mlp_kernel<<<GU_BLOCKS + DN_BLOCKS, 256, gemm_smem>>>(out);
}

// round 15
// speedup vs baseline: 1.9868x; 1.8045x over previous
#include <cuda_runtime.h>
#include <cuda_fp16.h>
#include <cstdint>

// Qwen3MoeMLP: out = down( silu(x @ gate^T) * (x @ up^T) )
// T=8192, H=2048, I=768, fp32 in/out.
// R15: FP16 HMMA (m16n8k16) — 2x the tf32 rate on the legacy tensor pipe,
//      SAME 11-bit mantissa as tf32 (rel_err ~4.9e-4), half the operand
//      traffic (the R12 kernel was L1-bandwidth co-bound).
//      Structure = R12 (best known): fused single GEMM launch with rowblock
//      release/acquire counters, 4-stage cp.async B-ring, A via LDG.128
//      register pipeline, fragment-packed operands produced by prep.

#define T_DIM 8192
#define H_DIM 2048
#define I_DIM 768
#define KH16  (H_DIM / 16)    // 128 k16-tiles over H
#define KI16  (I_DIM / 16)    // 48  k16-tiles over I
#define KT1   (H_DIM / 64)    // 32 kt-iterations (gateup), 4 k16 per kt
#define KT2   (I_DIM / 64)    // 12 kt-iterations (down)
#define BSTAGE 16384          // 16 nt x 4 k16 x 32 lanes x 8B
#define NSTG   4
#define GU_BLOCKS 768         // 64 bm x 12 bn (N = 2*I interleaved / 128)
#define DN_BLOCKS 1024        // 64 bm x 16 bn (N = H / 128)

// Static device scratch (no allocations allowed). All operands fp16.
// A-pack: [mt][k16][lane][8 fp16 = 16B]  (m16k16 fragments: a0,a1,a2,a3)
// B-pack: [nt][k16][lane][4 fp16 = 8B]   (n8k16 fragments: b0,b1)
// g_wgu interleaves gate/up: nt = 2q -> gate tile q, 2q+1 -> up tile q.
__device__ __align__(256) __half g_xa [(size_t)T_DIM * H_DIM];
__device__ __align__(256) __half g_wgu[(size_t)2 * I_DIM * H_DIM];
__device__ __align__(256) __half g_wdb[(size_t)H_DIM * I_DIM];
__device__ __align__(256) __half g_ha [(size_t)T_DIM * I_DIM];
__device__ unsigned g_cnt[64];          // rowblock completion counters

__device__ __forceinline__ uint32_t f2h2(float lo, float hi) {
    __half2 h = __floats2half2_rn(lo, hi);
    return *(uint32_t*)&h;
}
__device__ __forceinline__ void cp16(uint32_t s, const void* g) {
    asm volatile("cp.async.cg.shared.global [%0], [%1], 16;\n" :: "r"(s), "l"(g));
}
__device__ __forceinline__ void cp_commit() {
    asm volatile("cp.async.commit_group;\n" ::);
}
template <int N>
__device__ __forceinline__ void cp_wait() {
    asm volatile("cp.async.wait_group %0;\n" :: "n"(N));
}
__device__ __forceinline__ uint2 lds64(uint32_t a) {
    uint2 v;
    asm volatile("ld.shared.v2.b32 {%0,%1}, [%2];" : "=r"(v.x), "=r"(v.y) : "r"(a));
    return v;
}
// m16n8k16 fp16 x fp16 -> fp32
__device__ __forceinline__ void mma16(float* c, const uint4 a, const uint2 b) {
    asm volatile(
        "mma.sync.aligned.m16n8k16.row.col.f32.f16.f16.f32 "
        "{%0,%1,%2,%3}, {%4,%5,%6,%7}, {%8,%9}, {%0,%1,%2,%3};\n"
        : "+f"(c[0]), "+f"(c[1]), "+f"(c[2]), "+f"(c[3])
        : "r"(a.x), "r"(a.y), "r"(a.z), "r"(a.w), "r"(b.x), "r"(b.y));
}

// ============================================================================
// Prep: convert fp32 -> fp16 fragments (coalesced smem staging, raw fp32 in
// smem; the half conversion IS the rounding).
// Blocks [0,2048): X. [2048,3584): Wg/Wu interleaved. [3584,4352): Wd.
// Also resets rowblock counters (graph replays reuse them).
// ============================================================================
__global__ void __launch_bounds__(256)
prep_kernel(const float* __restrict__ X,  const float* __restrict__ Wg,
            const float* __restrict__ Wu, const float* __restrict__ Wd)
{
    extern __shared__ float sm[];
    const int tid = threadIdx.x;
    const int bid = blockIdx.x;

    if (bid == 0 && tid < 64) g_cnt[tid] = 0;

    if (bid < 2048) {
        // ---- X -> A-pack ----
        const int mt = bid >> 2;        // 0..511 (m16 tiles)
        const int kc = bid & 3;         // 512-col chunk (= 32 k16-tiles)
        const float* src = X + (size_t)mt * 16 * H_DIM + kc * 512;
#pragma unroll
        for (int i = 0; i < 8; i++) {
            const int q = tid + 256 * i;
            const int r = q >> 7, c4 = q & 127;
            *(float4*)(sm + r * 516 + c4 * 4) =
                __ldg((const float4*)(src + (size_t)r * H_DIM) + c4);
        }
        __syncthreads();
#pragma unroll
        for (int i = 0; i < 4; i++) {   // 1024 fragments x 16B
            const int f = tid + 256 * i;
            const int ktl = f >> 5, lane = f & 31;
            const int g = lane >> 2, tg = lane & 3;
            const int c = ktl * 16 + 2 * tg;
            uint4 v;
            v.x = f2h2(sm[g * 516 + c],           sm[g * 516 + c + 1]);
            v.y = f2h2(sm[(g + 8) * 516 + c],     sm[(g + 8) * 516 + c + 1]);
            v.z = f2h2(sm[g * 516 + c + 8],       sm[g * 516 + c + 9]);
            v.w = f2h2(sm[(g + 8) * 516 + c + 8], sm[(g + 8) * 516 + c + 9]);
            ((uint4*)g_xa)[((size_t)mt * KH16 + kc * 32 + ktl) * 32 + lane] = v;
        }
    } else {
        // ---- W -> B-pack ----
        const int b2 = bid - 2048;
        const float* W;
        __half* dst;
        int LD, K16LD;
        size_t out_nt;
        int kc;
        if (b2 < 1536) {
            const int sel = (b2 < 768) ? 0 : 1;     // 0=gate, 1=up
            W = sel ? Wu : Wg;
            dst = g_wgu;
            LD = H_DIM; K16LD = KH16;
            const int r = (b2 < 768) ? b2 : b2 - 768;   // NOT & 767 (768 != 2^n)
            const int nt = r >> 3;                  // 0..95
            kc = r & 7;                             // 8 chunks x 256 cols (16 k16)
            out_nt = 2 * (size_t)nt + sel;          // interleave
            W += (size_t)nt * 8 * LD;
        } else {
            W = Wd; dst = g_wdb;
            LD = I_DIM; K16LD = KI16;
            const int r = b2 - 1536;
            const int nt = r / 3;                   // 0..255
            kc = r % 3;                             // 3 chunks x 256 cols
            out_nt = (size_t)nt;
            W += (size_t)nt * 8 * LD;
        }
        const float* src = W + kc * 256;
#pragma unroll
        for (int i = 0; i < 2; i++) {
            const int q = tid + 256 * i;
            const int r = q >> 6, c4 = q & 63;
            *(float4*)(sm + r * 260 + c4 * 4) =
                __ldg((const float4*)(src + (size_t)r * LD) + c4);
        }
        __syncthreads();
#pragma unroll
        for (int i = 0; i < 2; i++) {   // 512 fragments x 8B
            const int f = tid + 256 * i;
            const int ktl = f >> 5, lane = f & 31;  // ktl 0..15
            const int g = lane >> 2, tg = lane & 3;
            const int c = ktl * 16 + 2 * tg;
            uint2 v;
            v.x = f2h2(sm[g * 260 + c],     sm[g * 260 + c + 1]);
            v.y = f2h2(sm[g * 260 + c + 8], sm[g * 260 + c + 9]);
            ((uint2*)dst)[(out_nt * K16LD + kc * 16 + ktl) * 32 + lane] = v;
        }
    }
}

// ============================================================================
// GEMM body: C tile 128 x 128, mt=2 x nt=8 per warp, m16n8k16 fp16 MMAs.
// BK=64 (4 k16) per stage. A via LDG.128 register pipeline (2 k16 deep);
// B via 4-stage cp.async ring (16KB/stage).
// GU: A=g_xa, B=g_wgu (interleaved), SiLU-pair epilogue -> g_ha; release cnt.
// DN: B prefetch first, acquire-spin on cnt, A=g_ha, B=g_wdb -> Out (fp32).
// ============================================================================
template <int K16S, int KT, bool GU>
__device__ __forceinline__ void gemm_body(int bid, uint32_t sb, float* __restrict__ Out)
{
    const int tid  = threadIdx.x;
    const int lane = tid & 31;
    const int warp = tid >> 5;
    const int wm = warp & 3;
    const int wn = warp >> 2;
    const int g  = lane >> 2;
    const int tg = lane & 3;

    const int NBN = GU ? 12 : 16;
    const int bmblk = bid / NBN;
    const int bnblk = bid % NBN;
    const size_t mt0 = (size_t)bmblk * 8;
    const size_t nt0 = (size_t)bnblk * 16;

    const uint4* Apack = (const uint4*)(GU ? g_xa : g_ha);
    const uint2* Bpack = (const uint2*)(GU ? g_wgu : g_wdb);

    // Stage layout: [ntl(16)][k16(4)][lane(32)] x 8B = 16KB.
    auto load_B = [&](int s, int ktL) {
        const uint32_t st = sb + s * BSTAGE;
#pragma unroll
        for (int i = 0; i < 4; i++) {
            const int q = tid + 256 * i;                 // 0..1023 granules of 16B
            const int pr = q & 15, k16 = (q >> 4) & 3, ntl = q >> 6;
            const uint2* src = Bpack +
                (((size_t)(nt0 + ntl) * K16S + (size_t)ktL * 4 + k16) * 32 + pr * 2);
            cp16(st + q * 16, src);
        }
    };

    // Weight/B prefetch does not depend on gateup output -> issue before acquire.
    load_B(0, 0); cp_commit();
    load_B(1, 1); cp_commit();
    load_B(2, 2); cp_commit();

    if (!GU) {
        // Acquire: wait until all 12 gateup tiles of this rowblock released.
        if (tid == 0) {
            unsigned v;
            const unsigned* p = &g_cnt[bmblk];
            do {
                asm volatile("ld.acquire.gpu.global.u32 %0, [%1];"
                             : "=r"(v) : "l"(p) : "memory");
                if (v < 12u) __nanosleep(128);
            } while (v < 12u);
        }
        __syncthreads();
    }

    const uint4* ap0 = Apack + ((mt0 + wm * 2 + 0) * K16S) * 32 + lane;
    const uint4* ap1 = Apack + ((mt0 + wm * 2 + 1) * K16S) * 32 + lane;

    float acc[2][8][4];
#pragma unroll
    for (int i = 0; i < 2; i++)
#pragma unroll
        for (int j = 0; j < 8; j++)
#pragma unroll
            for (int k = 0; k < 4; k++) acc[i][j][k] = 0.f;

    // A register pipeline, 2 k16 deep.
    const int LASTF = KT * 4 - 1;
    uint4 a0 = __ldg(ap0);
    uint4 a1 = __ldg(ap1);
    uint4 b0 = __ldg(ap0 + 32);
    uint4 b1 = __ldg(ap1 + 32);

    int sc = 0, sl = 3;
    for (int kt = 0; kt < KT; ++kt) {
        cp_wait<2>();
        __syncthreads();
        if (kt + 3 < KT) load_B(sl, kt + 3);
        cp_commit();
        const uint32_t sB = sb + sc * BSTAGE;
#pragma unroll
        for (int k16 = 0; k16 < 4; k16++) {
            int nf = kt * 4 + k16 + 2;
            if (nf > LASTF) nf = LASTF;
            uint4 c0 = __ldg(ap0 + (size_t)nf * 32);
            uint4 c1 = __ldg(ap1 + (size_t)nf * 32);
#pragma unroll
            for (int t = 0; t < 8; t++) {
                const int ntl = wn * 8 + t;
                uint2 b = lds64(sB + ((ntl * 4 + k16) * 32 + lane) * 8);
                mma16(acc[0][t], a0, b);
                mma16(acc[1][t], a1, b);
            }
            a0 = b0; a1 = b1; b0 = c0; b1 = c1;
        }
        if (++sc == NSTG) sc = 0;
        if (++sl == NSTG) sl = 0;
    }

    if (GU) {
        // h = silu(gate)*up -> fp16, written directly in down-A fragment order.
        // acc[tm][2j]=gate tile q, acc[tm][2j+1]=up tile q, q=bnblk*8+wn*4+j.
        // C frag: c0=(g,2tg) c1=(g,2tg+1) c2=(g+8,2tg) c3=(g+8,2tg+1).
        // Down-A fragment [mt_h][q>>1][lane'=g*4+tg]: uint2 slot (q&1):
        //   .x = rows g  cols 2tg,2tg+1 ; .y = rows g+8 cols 2tg,2tg+1.
#pragma unroll
        for (int tm = 0; tm < 2; tm++) {
#pragma unroll
            for (int j = 0; j < 4; j++) {
                const size_t mt_h = mt0 + wm * 2 + tm;
                const int q = bnblk * 8 + wn * 4 + j;
                float h[4];
#pragma unroll
                for (int i = 0; i < 4; i++) {
                    const float gv = acc[tm][2 * j][i];
                    const float uv = acc[tm][2 * j + 1][i];
                    h[i] = gv * uv / (1.0f + __expf(-gv));
                }
                uint2 hv;
                hv.x = f2h2(h[0], h[1]);
                hv.y = f2h2(h[2], h[3]);
                ((uint2*)g_ha)[((mt_h * KI16 + (q >> 1)) * 32 + (g * 4 + tg)) * 2
                               + (q & 1)] = hv;
            }
        }
        // Release: all stores visible, then bump rowblock counter.
        __threadfence();
        __syncthreads();
        if (tid == 0)
            asm volatile("red.release.gpu.global.add.u32 [%0], %1;"
                         :: "l"(&g_cnt[bmblk]), "r"(1u) : "memory");
    } else {
        const int bm = bmblk * 128;
        const int bn = bnblk * 128;
#pragma unroll
        for (int tm = 0; tm < 2; tm++) {
#pragma unroll
            for (int tn = 0; tn < 8; tn++) {
                const int r0 = bm + wm * 32 + tm * 16 + g;
                const int c0 = bn + wn * 64 + tn * 8 + 2 * tg;
                *(float2*)(Out + (size_t)r0 * H_DIM + c0) =
                    make_float2(acc[tm][tn][0], acc[tm][tn][1]);
                *(float2*)(Out + (size_t)(r0 + 8) * H_DIM + c0) =
                    make_float2(acc[tm][tn][2], acc[tm][tn][3]);
            }
        }
    }
}

__global__ void __launch_bounds__(256, 2)
mlp_kernel(float* __restrict__ Out)
{
    extern __shared__ __align__(16) char smem[];
    const uint32_t sb = (uint32_t)__cvta_generic_to_shared(smem);
    const int bid = blockIdx.x;
    if (bid < GU_BLOCKS) gemm_body<KH16, KT1, true >(bid, sb, Out);
    else                 gemm_body<KI16, KT2, false>(bid - GU_BLOCKS, sb, Out);
}

// ============================================================================
// Launch
// ============================================================================
extern "C" void kernel_launch(void* const* d_in, const int* in_sizes, int n_in,
                              void* d_out, int out_size)
{
    const float* x  = (const float*)d_in[0];
    const float* wg = (const float*)d_in[1];
    const float* wu = (const float*)d_in[2];
    const float* wd = (const float*)d_in[3];
    float* out = (float*)d_out;

    const int prep_smem = 16 * 516 * 4;       // 33024
    const int gemm_smem = NSTG * BSTAGE;      // 65536
    cudaFuncSetAttribute(prep_kernel, cudaFuncAttributeMaxDynamicSharedMemorySize, prep_smem);
    cudaFuncSetAttribute(mlp_kernel,  cudaFuncAttributeMaxDynamicSharedMemorySize, gemm_smem);

    prep_kernel<<<4352, 256, prep_smem>>>(x, wg, wu, wd);
    mlp_kernel<<<GU_BLOCKS + DN_BLOCKS, 256, gemm_smem>>>(out);
}